// round 12
// baseline (speedup 1.0000x reference)
#include <cuda_runtime.h>
#include <cuda_fp16.h>
#include <cstdint>
#include <cstddef>

#define DIM   768
#define NOUT  2304
#define RANK  16
#define MTOT  32768
#define BM    128
#define BN    64
#define BK    64
#define KT    12          // 768/64
#define STG_A 16384       // A: 128 rows * 128B
#define STGB  24576       // A(16K) + B(8K)
#define SMEM_TOTAL (512 + 2 * STGB)   // 49664 -> 3 CTAs/SM (regs<=85)

__device__ __align__(1024) __half g_wh[NOUT * DIM];
__device__ __align__(1024) __half g_xh[MTOT * DIM];

__device__ __forceinline__ uint32_t smem_u32(const void* p) {
    uint32_t a;
    asm("{ .reg .u64 t; cvta.to.shared.u64 t, %1; cvt.u32.u64 %0, t; }" : "=r"(a) : "l"(p));
    return a;
}
#define CP16(dst, src) \
    asm volatile("cp.async.cg.shared.global [%0], [%1], 16;" :: "r"(dst), "l"(src))
#define CP_COMMIT() asm volatile("cp.async.commit_group;" ::: "memory")
#define CP_WAIT0()  asm volatile("cp.async.wait_group 0;" ::: "memory")
#define LDSM_X4(r0, r1, r2, r3, addr) \
    asm volatile("ldmatrix.sync.aligned.m8n8.x4.shared.b16 {%0,%1,%2,%3}, [%4];" \
        : "=r"(r0), "=r"(r1), "=r"(r2), "=r"(r3) : "r"(addr))
#define MMA16816(c, a0, a1, a2, a3, b0v, b1v) \
    asm volatile("mma.sync.aligned.m16n8k16.row.col.f32.f16.f16.f32 " \
        "{%0,%1,%2,%3}, {%4,%5,%6,%7}, {%8,%9}, {%0,%1,%2,%3};" \
        : "+f"((c)[0]), "+f"((c)[1]), "+f"((c)[2]), "+f"((c)[3]) \
        : "r"(a0), "r"(a1), "r"(a2), "r"(a3), "r"(b0v), "r"(b1v))

// Merged prep: blocks [0, nConvBlk) convert x -> fp16; rest fold LoRA into fp16 Weff.
__global__ void prep_kernel(const float* __restrict__ x, int n8, int nConvBlk,
                            const float* __restrict__ W,
                            const float* __restrict__ Aq, const float* __restrict__ Bq,
                            const float* __restrict__ Ak, const float* __restrict__ Bk,
                            const float* __restrict__ Av, const float* __restrict__ Bv) {
    if (blockIdx.x < (unsigned)nConvBlk) {
        int i = blockIdx.x * 256 + threadIdx.x;
        if (i >= n8) return;
        float4 v0 = reinterpret_cast<const float4*>(x)[i * 2];
        float4 v1 = reinterpret_cast<const float4*>(x)[i * 2 + 1];
        __half2 h[4];
        h[0] = __float22half2_rn(make_float2(v0.x, v0.y));
        h[1] = __float22half2_rn(make_float2(v0.z, v0.w));
        h[2] = __float22half2_rn(make_float2(v1.x, v1.y));
        h[3] = __float22half2_rn(make_float2(v1.z, v1.w));
        reinterpret_cast<uint4*>(g_xh)[i] = *reinterpret_cast<uint4*>(h);
    } else {
        int idx = (blockIdx.x - nConvBlk) * 256 + threadIdx.x;
        if (idx >= NOUT * DIM) return;
        int o = idx / DIM;
        int d = idx - o * DIM;
        int s = o / DIM;
        int op = o - s * DIM;
        const float* A = (s == 0) ? Aq : (s == 1) ? Ak : Av;
        const float* B = (s == 0) ? Bq : (s == 1) ? Bk : Bv;
        float acc = W[idx];
#pragma unroll
        for (int r = 0; r < RANK; r++) acc += B[op * RANK + r] * A[r * DIM + d];
        g_wh[idx] = __float2half_rn(acc);
    }
}

// out[m][n] = sum_k xh[m][k] * wh[n][k] + bias[n]
// CTA 256 thr, tile 128x64, 8 warps 4(M)x2(N), warp tile 32x32, NSTG=2, 3 CTAs/SM (24 warps).
__global__ __launch_bounds__(256, 3) void gemm_f16(const float* __restrict__ bias,
                                                   float* __restrict__ out) {
    extern __shared__ __align__(1024) char smem[];
    float* bsm = reinterpret_cast<float*>(smem);
    const uint32_t sbase = smem_u32(smem + 512);

    const int tid = threadIdx.x;
    const int lane = tid & 31;
    const int wid = tid >> 5;
    const int wm = wid & 3;          // rows wm*32
    const int wn = wid >> 2;         // cols wn*32
    const int gm0 = blockIdx.y * BM;
    const int gn0 = blockIdx.x * BN;

    if (tid < BN) bsm[tid] = bias[gn0 + tid];

    // ---- cp.async addressing ----
    const int ldr = tid >> 3;            // 0..31
    const int ldc = tid & 7;
    const uint32_t soff0 = (uint32_t)(ldr * 128) + (uint32_t)(((ldc ^ (ldr & 7)) << 4));
    const __half* aSrc = g_xh + (size_t)(gm0 + ldr) * DIM + ldc * 8;
    const __half* bSrc = g_wh + (size_t)(gn0 + ldr) * DIM + ldc * 8;
    const size_t rstep = (size_t)32 * DIM;   // 32 rows per chunk step (r&7 invariant)

    // ---- ldmatrix bases ----
    const int rowA = wm * 32 + (lane & 15);
    const int rowB = wn * 32 + (lane & 15);
    const int cbh = lane >> 4;
    const uint32_t aBase = (uint32_t)(rowA * 128);
    const uint32_t bBase = (uint32_t)(rowB * 128);
    const int swzA = rowA & 7, swzB = rowB & 7;

    float acc[2][4][4];
#pragma unroll
    for (int i = 0; i < 2; i++)
#pragma unroll
        for (int n = 0; n < 4; n++)
#pragma unroll
            for (int t = 0; t < 4; t++) acc[i][n][t] = 0.0f;

    // prologue: stage 0 (A: 4 chunks, B: 2 chunks per thread)
#pragma unroll
    for (int i = 0; i < 4; i++)
        CP16(sbase + soff0 + i * 4096, aSrc + i * rstep);
#pragma unroll
    for (int i = 0; i < 2; i++)
        CP16(sbase + STG_A + soff0 + i * 4096, bSrc + i * rstep);
    CP_COMMIT();

    for (int kt = 0; kt < KT; kt++) {
        CP_WAIT0();
        __syncthreads();

        int nk = kt + 1;
        if (nk < KT) {
            uint32_t st = sbase + (nk & 1) * STGB;
#pragma unroll
            for (int i = 0; i < 4; i++)
                CP16(st + soff0 + i * 4096, aSrc + nk * BK + i * rstep);
#pragma unroll
            for (int i = 0; i < 2; i++)
                CP16(st + STG_A + soff0 + i * 4096, bSrc + nk * BK + i * rstep);
            CP_COMMIT();
        }

        const uint32_t stA = sbase + (kt & 1) * STGB;
        const uint32_t stB = stA + STG_A;

#pragma unroll
        for (int kk = 0; kk < 4; kk++) {
            const int cb = kk * 2 + cbh;
            const uint32_t aaddr = stA + aBase + (uint32_t)(((cb ^ swzA) << 4));
            const uint32_t baddr = stB + bBase + (uint32_t)(((cb ^ swzB) << 4));

            uint32_t af[2][4];
            LDSM_X4(af[0][0], af[0][1], af[0][2], af[0][3], aaddr);
            LDSM_X4(af[1][0], af[1][1], af[1][2], af[1][3], aaddr + 2048);

            uint32_t bf[2][4];
            LDSM_X4(bf[0][0], bf[0][1], bf[0][2], bf[0][3], baddr);
            LDSM_X4(bf[1][0], bf[1][1], bf[1][2], bf[1][3], baddr + 2048);

#pragma unroll
            for (int n = 0; n < 4; n++) {
                const int g = n >> 1, h = n & 1;
#pragma unroll
                for (int i = 0; i < 2; i++)
                    MMA16816(acc[i][n], af[i][0], af[i][1], af[i][2], af[i][3],
                             bf[g][h], bf[g][h + 2]);
            }
        }
    }

    // Epilogue: float2 stores, bias from smem
    const int r0 = wm * 32 + (lane >> 2);
    const int c0 = wn * 32 + (lane & 3) * 2;
    float* ob = out + (size_t)gm0 * NOUT + gn0;
#pragma unroll
    for (int i = 0; i < 2; i++) {
        int row = r0 + i * 16;
#pragma unroll
        for (int n = 0; n < 4; n++) {
            int col = c0 + n * 8;
            float b0 = bsm[col], b1 = bsm[col + 1];
            float2 v0 = make_float2(acc[i][n][0] + b0, acc[i][n][1] + b1);
            float2 v1 = make_float2(acc[i][n][2] + b0, acc[i][n][3] + b1);
            *reinterpret_cast<float2*>(ob + (size_t)row * NOUT + col) = v0;
            *reinterpret_cast<float2*>(ob + (size_t)(row + 8) * NOUT + col) = v1;
        }
    }
}

extern "C" void kernel_launch(void* const* d_in, const int* in_sizes, int n_in,
                              void* d_out, int out_size) {
    const float* x    = (const float*)d_in[0];
    const float* Wqkv = (const float*)d_in[1];
    const float* bqkv = (const float*)d_in[2];
    const float* Aq   = (const float*)d_in[3];
    const float* Bq   = (const float*)d_in[4];
    const float* Ak   = (const float*)d_in[5];
    const float* Bk   = (const float*)d_in[6];
    const float* Av   = (const float*)d_in[7];
    const float* Bv   = (const float*)d_in[8];
    float* out = (float*)d_out;

    int M = in_sizes[0] / DIM;   // 32768
    cudaFuncSetAttribute(gemm_f16, cudaFuncAttributeMaxDynamicSharedMemorySize, SMEM_TOTAL);

    int n8 = M * DIM / 8;
    int nConvBlk = (n8 + 255) / 256;
    int nFoldBlk = (NOUT * DIM + 255) / 256;
    prep_kernel<<<nConvBlk + nFoldBlk, 256>>>(x, n8, nConvBlk, Wqkv, Aq, Bq, Ak, Bk, Av, Bv);

    dim3 grid(NOUT / BN, M / BM);   // 36 x 256
    gemm_f16<<<grid, 256, SMEM_TOTAL>>>(bqkv, out);
}

// round 13
// speedup vs baseline: 1.0026x; 1.0026x over previous
#include <cuda_runtime.h>
#include <cuda_fp16.h>
#include <cstdint>
#include <cstddef>

#define DIM   768
#define NOUT  2304
#define RANK  16
#define MTOT  32768
#define BM    128
#define BN    64
#define BK    64
#define KT    12          // 768/64
#define STG_A 16384       // A: 128 rows * 128B
#define STGB  24576       // A(16K) + B(8K)
#define SMEM_TOTAL (512 + 2 * STGB)   // 49664 -> 3 CTAs/SM (regs<=85)

__device__ __align__(1024) __half g_wh[NOUT * DIM];
__device__ __align__(1024) __half g_xh[MTOT * DIM];

__device__ __forceinline__ uint32_t smem_u32(const void* p) {
    uint32_t a;
    asm("{ .reg .u64 t; cvta.to.shared.u64 t, %1; cvt.u32.u64 %0, t; }" : "=r"(a) : "l"(p));
    return a;
}
#define CP16(dst, src) \
    asm volatile("cp.async.cg.shared.global [%0], [%1], 16;" :: "r"(dst), "l"(src))
#define CP_COMMIT() asm volatile("cp.async.commit_group;" ::: "memory")
#define CP_WAIT0()  asm volatile("cp.async.wait_group 0;" ::: "memory")
#define LDSM_X4(r0, r1, r2, r3, addr) \
    asm volatile("ldmatrix.sync.aligned.m8n8.x4.shared.b16 {%0,%1,%2,%3}, [%4];" \
        : "=r"(r0), "=r"(r1), "=r"(r2), "=r"(r3) : "r"(addr))
#define MMA16816(c, a0, a1, a2, a3, b0v, b1v) \
    asm volatile("mma.sync.aligned.m16n8k16.row.col.f32.f16.f16.f32 " \
        "{%0,%1,%2,%3}, {%4,%5,%6,%7}, {%8,%9}, {%0,%1,%2,%3};" \
        : "+f"((c)[0]), "+f"((c)[1]), "+f"((c)[2]), "+f"((c)[3]) \
        : "r"(a0), "r"(a1), "r"(a2), "r"(a3), "r"(b0v), "r"(b1v))

// Merged prep: blocks [0, nConvBlk) convert x -> fp16; rest fold LoRA into fp16 Weff.
__global__ void prep_kernel(const float* __restrict__ x, int n8, int nConvBlk,
                            const float* __restrict__ W,
                            const float* __restrict__ Aq, const float* __restrict__ Bq,
                            const float* __restrict__ Ak, const float* __restrict__ Bk,
                            const float* __restrict__ Av, const float* __restrict__ Bv) {
    if (blockIdx.x < (unsigned)nConvBlk) {
        int i = blockIdx.x * 256 + threadIdx.x;
        if (i >= n8) return;
        float4 v0 = reinterpret_cast<const float4*>(x)[i * 2];
        float4 v1 = reinterpret_cast<const float4*>(x)[i * 2 + 1];
        __half2 h[4];
        h[0] = __float22half2_rn(make_float2(v0.x, v0.y));
        h[1] = __float22half2_rn(make_float2(v0.z, v0.w));
        h[2] = __float22half2_rn(make_float2(v1.x, v1.y));
        h[3] = __float22half2_rn(make_float2(v1.z, v1.w));
        reinterpret_cast<uint4*>(g_xh)[i] = *reinterpret_cast<uint4*>(h);
    } else {
        int idx = (blockIdx.x - nConvBlk) * 256 + threadIdx.x;
        if (idx >= NOUT * DIM) return;
        int o = idx / DIM;
        int d = idx - o * DIM;
        int s = o / DIM;
        int op = o - s * DIM;
        const float* A = (s == 0) ? Aq : (s == 1) ? Ak : Av;
        const float* B = (s == 0) ? Bq : (s == 1) ? Bk : Bv;
        float acc = W[idx];
#pragma unroll
        for (int r = 0; r < RANK; r++) acc += B[op * RANK + r] * A[r * DIM + d];
        g_wh[idx] = __float2half_rn(acc);
    }
}

// out[m][n] = sum_k xh[m][k] * wh[n][k] + bias[n]
// CTA 256 thr, tile 128x64, 8 warps 4(M)x2(N), warp tile 32x32, NSTG=2, 3 CTAs/SM (24 warps).
__global__ __launch_bounds__(256, 3) void gemm_f16(const float* __restrict__ bias,
                                                   float* __restrict__ out) {
    extern __shared__ __align__(1024) char smem[];
    float* bsm = reinterpret_cast<float*>(smem);
    const uint32_t sbase = smem_u32(smem + 512);

    const int tid = threadIdx.x;
    const int lane = tid & 31;
    const int wid = tid >> 5;
    const int wm = wid & 3;          // rows wm*32
    const int wn = wid >> 2;         // cols wn*32
    const int gm0 = blockIdx.y * BM;
    const int gn0 = blockIdx.x * BN;

    if (tid < BN) bsm[tid] = bias[gn0 + tid];

    // ---- cp.async addressing ----
    const int ldr = tid >> 3;            // 0..31
    const int ldc = tid & 7;
    const uint32_t soff0 = (uint32_t)(ldr * 128) + (uint32_t)(((ldc ^ (ldr & 7)) << 4));
    const __half* aSrc = g_xh + (size_t)(gm0 + ldr) * DIM + ldc * 8;
    const __half* bSrc = g_wh + (size_t)(gn0 + ldr) * DIM + ldc * 8;
    const size_t rstep = (size_t)32 * DIM;   // 32 rows per chunk step (r&7 invariant)

    // ---- ldmatrix bases ----
    const int rowA = wm * 32 + (lane & 15);
    const int rowB = wn * 32 + (lane & 15);
    const int cbh = lane >> 4;
    const uint32_t aBase = (uint32_t)(rowA * 128);
    const uint32_t bBase = (uint32_t)(rowB * 128);
    const int swzA = rowA & 7, swzB = rowB & 7;

    float acc[2][4][4];
#pragma unroll
    for (int i = 0; i < 2; i++)
#pragma unroll
        for (int n = 0; n < 4; n++)
#pragma unroll
            for (int t = 0; t < 4; t++) acc[i][n][t] = 0.0f;

    // prologue: stage 0 (A: 4 chunks, B: 2 chunks per thread)
#pragma unroll
    for (int i = 0; i < 4; i++)
        CP16(sbase + soff0 + i * 4096, aSrc + i * rstep);
#pragma unroll
    for (int i = 0; i < 2; i++)
        CP16(sbase + STG_A + soff0 + i * 4096, bSrc + i * rstep);
    CP_COMMIT();

    for (int kt = 0; kt < KT; kt++) {
        CP_WAIT0();
        __syncthreads();

        int nk = kt + 1;
        if (nk < KT) {
            uint32_t st = sbase + (nk & 1) * STGB;
#pragma unroll
            for (int i = 0; i < 4; i++)
                CP16(st + soff0 + i * 4096, aSrc + nk * BK + i * rstep);
#pragma unroll
            for (int i = 0; i < 2; i++)
                CP16(st + STG_A + soff0 + i * 4096, bSrc + nk * BK + i * rstep);
            CP_COMMIT();
        }

        const uint32_t stA = sbase + (kt & 1) * STGB;
        const uint32_t stB = stA + STG_A;

#pragma unroll
        for (int kk = 0; kk < 4; kk++) {
            const int cb = kk * 2 + cbh;
            const uint32_t aaddr = stA + aBase + (uint32_t)(((cb ^ swzA) << 4));
            const uint32_t baddr = stB + bBase + (uint32_t)(((cb ^ swzB) << 4));

            uint32_t af[2][4];
            LDSM_X4(af[0][0], af[0][1], af[0][2], af[0][3], aaddr);
            LDSM_X4(af[1][0], af[1][1], af[1][2], af[1][3], aaddr + 2048);

            uint32_t bf[2][4];
            LDSM_X4(bf[0][0], bf[0][1], bf[0][2], bf[0][3], baddr);
            LDSM_X4(bf[1][0], bf[1][1], bf[1][2], bf[1][3], baddr + 2048);

#pragma unroll
            for (int n = 0; n < 4; n++) {
                const int g = n >> 1, h = n & 1;
#pragma unroll
                for (int i = 0; i < 2; i++)
                    MMA16816(acc[i][n], af[i][0], af[i][1], af[i][2], af[i][3],
                             bf[g][h], bf[g][h + 2]);
            }
        }
    }

    // Epilogue: float2 stores, bias from smem
    const int r0 = wm * 32 + (lane >> 2);
    const int c0 = wn * 32 + (lane & 3) * 2;
    float* ob = out + (size_t)gm0 * NOUT + gn0;
#pragma unroll
    for (int i = 0; i < 2; i++) {
        int row = r0 + i * 16;
#pragma unroll
        for (int n = 0; n < 4; n++) {
            int col = c0 + n * 8;
            float b0 = bsm[col], b1 = bsm[col + 1];
            float2 v0 = make_float2(acc[i][n][0] + b0, acc[i][n][1] + b1);
            float2 v1 = make_float2(acc[i][n][2] + b0, acc[i][n][3] + b1);
            *reinterpret_cast<float2*>(ob + (size_t)row * NOUT + col) = v0;
            *reinterpret_cast<float2*>(ob + (size_t)(row + 8) * NOUT + col) = v1;
        }
    }
}

extern "C" void kernel_launch(void* const* d_in, const int* in_sizes, int n_in,
                              void* d_out, int out_size) {
    const float* x    = (const float*)d_in[0];
    const float* Wqkv = (const float*)d_in[1];
    const float* bqkv = (const float*)d_in[2];
    const float* Aq   = (const float*)d_in[3];
    const float* Bq   = (const float*)d_in[4];
    const float* Ak   = (const float*)d_in[5];
    const float* Bk   = (const float*)d_in[6];
    const float* Av   = (const float*)d_in[7];
    const float* Bv   = (const float*)d_in[8];
    float* out = (float*)d_out;

    int M = in_sizes[0] / DIM;   // 32768
    cudaFuncSetAttribute(gemm_f16, cudaFuncAttributeMaxDynamicSharedMemorySize, SMEM_TOTAL);

    int n8 = M * DIM / 8;
    int nConvBlk = (n8 + 255) / 256;
    int nFoldBlk = (NOUT * DIM + 255) / 256;
    prep_kernel<<<nConvBlk + nFoldBlk, 256>>>(x, n8, nConvBlk, Wqkv, Aq, Bq, Ak, Bk, Av, Bv);

    dim3 grid(NOUT / BN, M / BM);   // 36 x 256
    gemm_f16<<<grid, 256, SMEM_TOTAL>>>(bqkv, out);
}